// round 1
// baseline (speedup 1.0000x reference)
#include <cuda_runtime.h>

// SlidingVariance: x (B=32, L=16384, C=1) fp32, w=64.
// out[b,i] = population variance of x[b, i : min(i+w, L)].
// Trick: zero-fill shared beyond L, sum full w elements -> equals masked sums;
// divide by n = min(w, L-i).

#define W 64
#define TILE 256
#define THREADS 256

__global__ void sliding_var_kernel(const float* __restrict__ x,
                                   float* __restrict__ out,
                                   int L) {
    __shared__ float sh[TILE + W];

    const int b  = blockIdx.y;
    const int t0 = blockIdx.x * TILE;
    const long base = (long)b * L;

    // Stage TILE + W elements (the last W-1 are halo; zero past L).
    #pragma unroll
    for (int k = threadIdx.x; k < TILE + W; k += THREADS) {
        int idx = t0 + k;
        sh[k] = (idx < L) ? x[base + idx] : 0.0f;
    }
    __syncthreads();

    const int i = t0 + threadIdx.x;
    if (i < L) {
        float s = 0.0f, s2 = 0.0f;
        #pragma unroll
        for (int j = 0; j < W; j++) {
            float v = sh[threadIdx.x + j];
            s  += v;
            s2 = fmaf(v, v, s2);
        }
        int n = min(W, L - i);
        float inv_n = 1.0f / (float)n;
        float mean = s * inv_n;
        out[base + i] = fmaf(-mean, mean, s2 * inv_n);
    }
}

extern "C" void kernel_launch(void* const* d_in, const int* in_sizes, int n_in,
                              void* d_out, int out_size) {
    const float* x = (const float*)d_in[0];
    float* out = (float*)d_out;

    // Fixed problem shape: B=32, L=16384, C=1, w=64.
    const int B = 32;
    const int L = 16384;

    dim3 grid((L + TILE - 1) / TILE, B);
    sliding_var_kernel<<<grid, THREADS>>>(x, out, L);
}

// round 2
// speedup vs baseline: 1.2353x; 1.2353x over previous
#include <cuda_runtime.h>

// SlidingVariance: x (B=32, L=16384, C=1) fp32, w=64.
// out[b,i] = population variance of x[b, i : min(i+w, L)].
//
// Register-blocked rolling sums: each thread produces OPT consecutive
// outputs. First window summed once (vectorized LDS.128), subsequent
// windows updated incrementally: s += v_new - v_old, s2 += v_new^2 - v_old^2.
// Shared is zero-filled past L so full-width sums equal masked sums.

#define W       64
#define OPT     8
#define THREADS 256
#define TILE    (THREADS * OPT)   // 2048

__global__ void sliding_var_kernel(const float* __restrict__ x,
                                   float* __restrict__ out,
                                   int L) {
    __shared__ float sh[TILE + W];

    const int b  = blockIdx.y;
    const int t0 = blockIdx.x * TILE;
    const float* xb = x + (long)b * L;

    // Stage TILE + W floats via float4 (zero past L).
    const int NV4 = (TILE + W) / 4;   // 528
    for (int k = threadIdx.x; k < NV4; k += THREADS) {
        int idx = t0 + k * 4;
        float4 v;
        if (idx + 3 < L) {
            v = *reinterpret_cast<const float4*>(xb + idx);
        } else {
            v.x = (idx + 0 < L) ? xb[idx + 0] : 0.0f;
            v.y = (idx + 1 < L) ? xb[idx + 1] : 0.0f;
            v.z = (idx + 2 < L) ? xb[idx + 2] : 0.0f;
            v.w = (idx + 3 < L) ? xb[idx + 3] : 0.0f;
        }
        *reinterpret_cast<float4*>(&sh[k * 4]) = v;
    }
    __syncthreads();

    const int base = threadIdx.x * OPT;   // 32B-aligned in shared

    // Initial window sums over sh[base .. base+W-1], vectorized.
    float s = 0.0f, s2 = 0.0f;
    {
        const float4* sh4 = reinterpret_cast<const float4*>(&sh[base]);
        #pragma unroll
        for (int j = 0; j < W / 4; j++) {
            float4 v = sh4[j];
            s += (v.x + v.y) + (v.z + v.w);
            s2 = fmaf(v.x, v.x, s2);
            s2 = fmaf(v.y, v.y, s2);
            s2 = fmaf(v.z, v.z, s2);
            s2 = fmaf(v.w, v.w, s2);
        }
    }

    float sv[OPT], qv[OPT];
    sv[0] = s; qv[0] = s2;
    #pragma unroll
    for (int k = 1; k < OPT; k++) {
        float vold = sh[base + k - 1];
        float vnew = sh[base + k + W - 1];
        s  += vnew - vold;
        s2  = fmaf(vnew, vnew, fmaf(-vold, vold, s2));
        sv[k] = s; qv[k] = s2;
    }

    // Epilogue: variance = s2/n - (s/n)^2.
    float4 o[2];
    float* ro = reinterpret_cast<float*>(o);
    if (t0 + TILE + W <= L) {
        // Fast path: every window fully in-bounds, n == W.
        const float inv = 1.0f / (float)W;
        #pragma unroll
        for (int k = 0; k < OPT; k++) {
            float m = sv[k] * inv;
            ro[k] = fmaf(-m, m, qv[k] * inv);
        }
    } else {
        #pragma unroll
        for (int k = 0; k < OPT; k++) {
            int i = t0 + base + k;
            if (i < L) {
                int n = min(W, L - i);
                float inv = 1.0f / (float)n;
                float m = sv[k] * inv;
                ro[k] = fmaf(-m, m, qv[k] * inv);
            } else {
                ro[k] = 0.0f;
            }
        }
    }

    // L % TILE == 0 for this shape, so all OPT outputs are valid.
    float4* op = reinterpret_cast<float4*>(out + (long)b * L + t0 + base);
    op[0] = o[0];
    op[1] = o[1];
}

extern "C" void kernel_launch(void* const* d_in, const int* in_sizes, int n_in,
                              void* d_out, int out_size) {
    const float* x = (const float*)d_in[0];
    float* out = (float*)d_out;

    const int B = 32;
    const int L = 16384;

    dim3 grid((L + TILE - 1) / TILE, B);
    sliding_var_kernel<<<grid, THREADS>>>(x, out, L);
}

// round 3
// speedup vs baseline: 1.6232x; 1.3140x over previous
#include <cuda_runtime.h>

// SlidingVariance: x (B=32, L=16384, C=1) fp32, w=64.
// out[b,i] = population variance of x[b, i : min(i+w, L)].
//
// Rolling-sum register blocking (OPT=4 outputs/thread) with a small TILE
// and large grid (1024 blocks) to keep all SMs latency-hidden.

#define W       64
#define OPT     4
#define THREADS 128
#define TILE    (THREADS * OPT)   // 512

__global__ __launch_bounds__(THREADS)
void sliding_var_kernel(const float* __restrict__ x,
                        float* __restrict__ out,
                        int L) {
    __shared__ float sh[TILE + W];

    const int b  = blockIdx.y;
    const int t0 = blockIdx.x * TILE;
    const float* xb = x + (long)b * L;

    // Stage TILE + W floats via float4 (zero past L).
    const int NV4 = (TILE + W) / 4;   // 144
    #pragma unroll
    for (int k = threadIdx.x; k < NV4; k += THREADS) {
        int idx = t0 + k * 4;
        float4 v;
        if (idx + 3 < L) {
            v = *reinterpret_cast<const float4*>(xb + idx);
        } else {
            v.x = (idx + 0 < L) ? xb[idx + 0] : 0.0f;
            v.y = (idx + 1 < L) ? xb[idx + 1] : 0.0f;
            v.z = (idx + 2 < L) ? xb[idx + 2] : 0.0f;
            v.w = (idx + 3 < L) ? xb[idx + 3] : 0.0f;
        }
        *reinterpret_cast<float4*>(&sh[k * 4]) = v;
    }
    __syncthreads();

    const int base = threadIdx.x * OPT;   // 16B-aligned in shared

    // Initial window sums over sh[base .. base+W-1]; two accumulator
    // pairs to shorten the FMA dependency chain.
    float sA = 0.0f, sB = 0.0f, qA = 0.0f, qB = 0.0f;
    {
        const float4* sh4 = reinterpret_cast<const float4*>(&sh[base]);
        #pragma unroll
        for (int j = 0; j < W / 4; j += 2) {
            float4 u = sh4[j];
            float4 v = sh4[j + 1];
            sA += (u.x + u.y) + (u.z + u.w);
            sB += (v.x + v.y) + (v.z + v.w);
            qA = fmaf(u.x, u.x, qA);
            qA = fmaf(u.y, u.y, qA);
            qA = fmaf(u.z, u.z, qA);
            qA = fmaf(u.w, u.w, qA);
            qB = fmaf(v.x, v.x, qB);
            qB = fmaf(v.y, v.y, qB);
            qB = fmaf(v.z, v.z, qB);
            qB = fmaf(v.w, v.w, qB);
        }
    }
    float s  = sA + sB;
    float s2 = qA + qB;

    float sv[OPT], qv[OPT];
    sv[0] = s; qv[0] = s2;
    #pragma unroll
    for (int k = 1; k < OPT; k++) {
        float vold = sh[base + k - 1];
        float vnew = sh[base + k + W - 1];
        s  += vnew - vold;
        s2  = fmaf(vnew, vnew, fmaf(-vold, vold, s2));
        sv[k] = s; qv[k] = s2;
    }

    // Epilogue: variance = s2/n - (s/n)^2.
    float4 o;
    float* ro = reinterpret_cast<float*>(&o);
    if (t0 + TILE + W <= L) {
        const float inv = 1.0f / (float)W;
        #pragma unroll
        for (int k = 0; k < OPT; k++) {
            float m = sv[k] * inv;
            ro[k] = fmaf(-m, m, qv[k] * inv);
        }
    } else {
        #pragma unroll
        for (int k = 0; k < OPT; k++) {
            int i = t0 + base + k;
            if (i < L) {
                int n = min(W, L - i);
                float inv = 1.0f / (float)n;
                float m = sv[k] * inv;
                ro[k] = fmaf(-m, m, qv[k] * inv);
            } else {
                ro[k] = 0.0f;
            }
        }
    }

    // L % TILE == 0 for this shape: all OPT outputs valid.
    *reinterpret_cast<float4*>(out + (long)b * L + t0 + base) = o;
}

extern "C" void kernel_launch(void* const* d_in, const int* in_sizes, int n_in,
                              void* d_out, int out_size) {
    const float* x = (const float*)d_in[0];
    float* out = (float*)d_out;

    const int B = 32;
    const int L = 16384;

    dim3 grid((L + TILE - 1) / TILE, B);   // (32, 32) = 1024 blocks
    sliding_var_kernel<<<grid, THREADS>>>(x, out, L);
}